// round 8
// baseline (speedup 1.0000x reference)
#include <cuda_runtime.h>
#include <cuda_fp16.h>
#include <math.h>
#include <stdint.h>

#define B_DIM   4096
#define ZDIM    128
#define IN_DIM  512
#define H_DIM   1024
#define SEQ_LEN 12
#define CAT     (IN_DIM + H_DIM)
#define LDO     (SEQ_LEN * IN_DIM)
#define N12     (2 * H_DIM)

typedef __half  f16;
typedef __half2 f162;

// ---------------- scratch (__device__ globals; no allocs allowed) -----------
__device__ float g_stf[B_DIM * H_DIM];
__device__ float g_spf[B_DIM * H_DIM];
__device__ float g_uf [B_DIM * H_DIM];

__device__ f16 g_tdh[B_DIM * LDO],    g_tdl[B_DIM * LDO];
__device__ f16 g_zh [B_DIM * ZDIM],   g_zl [B_DIM * ZDIM];
__device__ f16 g_sph[B_DIM * H_DIM],  g_spl[B_DIM * H_DIM];
__device__ f16 g_sth[B_DIM * H_DIM],  g_stl[B_DIM * H_DIM];
__device__ f16 g_rsh[B_DIM * H_DIM],  g_rsl[B_DIM * H_DIM];
__device__ f16 g_xh [B_DIM * IN_DIM], g_xl [B_DIM * IN_DIM];

// weights transposed to [N][K] fp16 (hi only — 2-term scheme)
__device__ f16 g_W12h[N12 * CAT];          // W1 rows then W2 rows
__device__ f16 g_W3h [H_DIM * CAT];
__device__ f16 g_Wbh [H_DIM * IN_DIM];
__device__ f16 g_Woh [IN_DIM * H_DIM];
__device__ f16 g_Wzh [IN_DIM * ZDIM];

enum { EPI_LIN = 0, EPI_BELTA = 1, EPI_SIGUR = 2, EPI_NEW = 3 };

// ---------------- prep kernels ---------------------------------------------
__global__ void zero_kernel(float* __restrict__ p, int n) {
    int i = blockIdx.x * blockDim.x + threadIdx.x;
    if (i < n) p[i] = 0.0f;
}

__global__ void asplit(const float* __restrict__ X, int n4,
                       f16* __restrict__ H, f16* __restrict__ L) {
    int i = blockIdx.x * blockDim.x + threadIdx.x;
    if (i >= n4) return;
    float4 v = ((const float4*)X)[i];
    f16 h0 = __float2half_rn(v.x), h1 = __float2half_rn(v.y);
    f16 h2 = __float2half_rn(v.z), h3 = __float2half_rn(v.w);
    f162 H0; H0.x = h0; H0.y = h1;
    f162 H1; H1.x = h2; H1.y = h3;
    f162 L0, L1;
    L0.x = __float2half_rn(v.x - __half2float(h0));
    L0.y = __float2half_rn(v.y - __half2float(h1));
    L1.x = __float2half_rn(v.z - __half2float(h2));
    L1.y = __float2half_rn(v.w - __half2float(h3));
    ((f162*)H)[2 * i] = H0; ((f162*)H)[2 * i + 1] = H1;
    ((f162*)L)[2 * i] = L0; ((f162*)L)[2 * i + 1] = L1;
}

__global__ void whalf(const float* __restrict__ W, int K, int N,
                      f16* __restrict__ Th) {
    __shared__ float t[32][33];
    const int n0 = blockIdx.x * 32, k0 = blockIdx.y * 32;
    const int tx = threadIdx.x, ty = threadIdx.y;   // (32, 8)
#pragma unroll
    for (int j = 0; j < 32; j += 8)
        t[ty + j][tx] = W[(size_t)(k0 + ty + j) * N + (n0 + tx)];
    __syncthreads();
#pragma unroll
    for (int j = 0; j < 32; j += 8)
        Th[(size_t)(n0 + ty + j) * K + (k0 + tx)] = __float2half_rn(t[tx][ty + j]);
}

// ---------------- PTX primitives --------------------------------------------
__device__ __forceinline__ uint32_t smem_u32(const void* p) {
    uint32_t a;
    asm("{ .reg .u64 t; cvta.to.shared.u64 t, %1; cvt.u32.u64 %0, t; }" : "=r"(a) : "l"(p));
    return a;
}

#define CP16(dst, src) \
    asm volatile("cp.async.ca.shared.global [%0], [%1], 16;" :: "r"(dst), "l"(src) : "memory")
#define CPCOMMIT() asm volatile("cp.async.commit_group;" ::: "memory")
#define CPWAIT1()  asm volatile("cp.async.wait_group 1;"  ::: "memory")

#define LDSM4(r, a) \
    asm volatile("ldmatrix.sync.aligned.m8n8.x4.shared.b16 {%0,%1,%2,%3}, [%4];" \
        : "=r"((r)[0]), "=r"((r)[1]), "=r"((r)[2]), "=r"((r)[3]) : "r"(a))

#define MMA(c, a, b0, b1) \
    asm volatile("mma.sync.aligned.m16n8k16.row.col.f32.f16.f16.f32 " \
        "{%0,%1,%2,%3}, {%4,%5,%6,%7}, {%8,%9}, {%0,%1,%2,%3};" \
        : "+f"((c)[0]), "+f"((c)[1]), "+f"((c)[2]), "+f"((c)[3]) \
        : "r"((a)[0]), "r"((a)[1]), "r"((a)[2]), "r"((a)[3]), "r"(b0), "r"(b1))

// ---------------- HMMA GEMM with fused epilogue -----------------------------
// CTA tile 256x128, 8 warps = 4(M) x 2(N), warp tile 64x64, occ 1.
#define KC      32
#define AROW80  80                       // padded row pitch (32 halfs + 16B pad)
#define TILE_A  (256 * AROW80)           // 20480 B (one of hi/lo)
#define TILE_BB (128 * AROW80)           // 10240 B
#define STAGE   (2 * TILE_A + TILE_BB)   // 51200 B
#define NSTG    3
#define SMEM_T  (NSTG * STAGE)           // 153600 B

template <int EPI>
__global__ __launch_bounds__(256, 1)
void tgemm(const f16* __restrict__ Ah1, const f16* __restrict__ Al1, int lda1, int K1,
           const f16* __restrict__ Ah2, const f16* __restrict__ Al2, int lda2, int K2,
           const f16* __restrict__ Bh,
           const float* __restrict__ bias, const float* __restrict__ bias2,
           const float* __restrict__ ex1, const float* __restrict__ ex2,
           float* __restrict__ Cf, int ldcf,
           f16* __restrict__ Ch, f16* __restrict__ Cl, int ldch)
{
    extern __shared__ __align__(128) char smem[];
    const uint32_t sb = smem_u32(smem);
    const int tid = threadIdx.x;
    const int bm = blockIdx.y * 256, bn = blockIdx.x * 128;
    const int Ktot = K1 + K2;
    const int KT = Ktot / KC;

    // --- async copy mapping ---
    // A hi/lo: each thread owns row `tid` (4 x 16B segs each)
    // B: thread pair -> row tid>>1, segs {cs, cs+1}
    const int brow = tid >> 1;
    const int bcs  = (tid & 1) * 2;

    auto issue = [&](int c, int s) {
        const int ks = c * KC;
        const f16 *ah, *al;
        if (ks < K1) {
            ah = Ah1 + (size_t)(bm + tid) * lda1 + ks;
            al = Al1 + (size_t)(bm + tid) * lda1 + ks;
        } else {
            ah = Ah2 + (size_t)(bm + tid) * lda2 + (ks - K1);
            al = Al2 + (size_t)(bm + tid) * lda2 + (ks - K1);
        }
        const uint32_t abase = sb + (uint32_t)s * STAGE + (uint32_t)tid * AROW80;
#pragma unroll
        for (int seg = 0; seg < 4; seg++) {
            const uint32_t off = (uint32_t)seg * 16u;
            CP16(abase + off,          ah + seg * 8);
            CP16(abase + TILE_A + off, al + seg * 8);
        }
        const f16* bh = Bh + (size_t)(bn + brow) * Ktot + ks;
        const uint32_t bbase = sb + (uint32_t)s * STAGE + 2 * TILE_A
                             + (uint32_t)brow * AROW80;
#pragma unroll
        for (int g = 0; g < 2; g++) {
            const int seg = bcs + g;
            CP16(bbase + (uint32_t)seg * 16u, bh + seg * 8);
        }
    };

    // --- mma fragment mapping ---
    const int warp = tid >> 5, lane = tid & 31;
    const int wm = (warp & 3) * 64;            // 4 warps along M, 64 rows each
    const int wn = (warp >> 2) * 64;           // 2 warps along N, 64 cols each
    const int lr = lane & 7;
    const uint32_t aBase = (uint32_t)(wm + lr + ((lane >> 3) & 1) * 8) * AROW80
                         + (uint32_t)(((lane >> 4) & 1) * 8) * 2;
    const uint32_t bBase = (uint32_t)(wn + lr + ((lane >> 4) & 1) * 8) * AROW80
                         + (uint32_t)(((lane >> 3) & 1) * 8) * 2;

    float acc[4][8][4];
#pragma unroll
    for (int mi = 0; mi < 4; mi++)
#pragma unroll
        for (int j = 0; j < 8; j++)
#pragma unroll
            for (int q = 0; q < 4; q++) acc[mi][j][q] = 0.0f;

    // --- 3-stage cp.async ring ---
    issue(0, 0); CPCOMMIT();
    issue(1, 1); CPCOMMIT();

    for (int c = 0; c < KT; c++) {
        CPWAIT1();
        __syncthreads();
        if (c + 2 < KT) issue(c + 2, (c + 2) % NSTG);
        CPCOMMIT();
        const uint32_t st = sb + (uint32_t)(c % NSTG) * STAGE;
#pragma unroll
        for (int k2 = 0; k2 < 2; k2++) {
            uint32_t ah[4][4], al[4][4];
#pragma unroll
            for (int mi = 0; mi < 4; mi++) {
                const uint32_t ao = st + aBase + (uint32_t)mi * (16 * AROW80)
                                  + (uint32_t)k2 * 32;
                LDSM4(ah[mi], ao);
                LDSM4(al[mi], ao + TILE_A);
            }
#pragma unroll
            for (int jj = 0; jj < 4; jj++) {
                uint32_t b4[4];
                const uint32_t bo = st + 2 * TILE_A + bBase
                                  + (uint32_t)jj * (16 * AROW80) + (uint32_t)k2 * 32;
                LDSM4(b4, bo);
#pragma unroll
                for (int mi = 0; mi < 4; mi++) {
                    MMA(acc[mi][2 * jj],     ah[mi], b4[0], b4[1]);
                    MMA(acc[mi][2 * jj],     al[mi], b4[0], b4[1]);
                    MMA(acc[mi][2 * jj + 1], ah[mi], b4[2], b4[3]);
                    MMA(acc[mi][2 * jj + 1], al[mi], b4[2], b4[3]);
                }
            }
        }
    }

    // --- epilogue ---
    const int r0 = bm + wm + (lane >> 2);
    const int c0 = bn + wn + 2 * (lane & 3);

    auto dopair = [&](int row, int col, float v0, float v1) {
        if (EPI == EPI_SIGUR) {
            if (col < H_DIM) {
                float2 bs = *(const float2*)(bias + col);
                v0 = 1.0f / (1.0f + __expf(-(v0 + bs.x)));
                v1 = 1.0f / (1.0f + __expf(-(v1 + bs.y)));
                *(float2*)(Cf + (size_t)row * ldcf + col) = make_float2(v0, v1);
            } else {
                const int cc = col - H_DIM;
                float2 bs = *(const float2*)(bias2 + cc);
                float2 e  = *(const float2*)(ex1 + (size_t)row * H_DIM + cc);
                v0 = e.x / (1.0f + __expf(-(v0 + bs.x)));
                v1 = e.y / (1.0f + __expf(-(v1 + bs.y)));
                f16 h0 = __float2half_rn(v0), h1 = __float2half_rn(v1);
                f162 hh; hh.x = h0; hh.y = h1;
                f162 ll;
                ll.x = __float2half_rn(v0 - __half2float(h0));
                ll.y = __float2half_rn(v1 - __half2float(h1));
                *(f162*)(Ch + (size_t)row * ldch + cc) = hh;
                *(f162*)(Cl + (size_t)row * ldch + cc) = ll;
            }
            return;
        }
        float2 bs = *(const float2*)(bias + col);
        v0 += bs.x; v1 += bs.y;
        if (EPI == EPI_BELTA) {
            float2 e = *(const float2*)(ex1 + (size_t)row * H_DIM + col);
            v0 = __expf(-fmaxf(v0, 0.0f)) * e.x;
            v1 = __expf(-fmaxf(v1, 0.0f)) * e.y;
        } else if (EPI == EPI_NEW) {
            float2 eu = *(const float2*)(ex1 + (size_t)row * H_DIM + col);
            float2 es = *(const float2*)(ex2 + (size_t)row * H_DIM + col);
            v0 = (1.0f - eu.x) * es.x + eu.x * tanhf(v0);
            v1 = (1.0f - eu.y) * es.y + eu.y * tanhf(v1);
        }
        if (Cf) *(float2*)(Cf + (size_t)row * ldcf + col) = make_float2(v0, v1);
        if (Ch) {
            f16 h0 = __float2half_rn(v0), h1 = __float2half_rn(v1);
            f162 hh; hh.x = h0; hh.y = h1;
            f162 ll;
            ll.x = __float2half_rn(v0 - __half2float(h0));
            ll.y = __float2half_rn(v1 - __half2float(h1));
            *(f162*)(Ch + (size_t)row * ldch + col) = hh;
            *(f162*)(Cl + (size_t)row * ldch + col) = ll;
        }
    };

#pragma unroll
    for (int mi = 0; mi < 4; mi++)
#pragma unroll
        for (int j = 0; j < 8; j++) {
            const int row = r0 + mi * 16;
            const int col = c0 + j * 8;
            dopair(row,     col, acc[mi][j][0], acc[mi][j][1]);
            dopair(row + 8, col, acc[mi][j][2], acc[mi][j][3]);
        }
}

// ---------------- host -------------------------------------------------------
extern "C" void kernel_launch(void* const* d_in, const int* in_sizes, int n_in,
                              void* d_out, int out_size)
{
    const float* z       = (const float*)d_in[0];
    const float* td      = (const float*)d_in[1];
    const float* W_belta = (const float*)d_in[2];
    const float* b_belta = (const float*)d_in[3];
    const float* W_z     = (const float*)d_in[4];
    const float* b_z     = (const float*)d_in[5];
    const float* W1      = (const float*)d_in[6];
    const float* b1      = (const float*)d_in[7];
    const float* W2      = (const float*)d_in[8];
    const float* b2      = (const float*)d_in[9];
    const float* W3      = (const float*)d_in[10];
    const float* b3      = (const float*)d_in[11];
    const float* W_out   = (const float*)d_in[12];
    const float* b_out   = (const float*)d_in[13];
    float* out = (float*)d_out;

    float *stf, *spf, *uf;
    cudaGetSymbolAddress((void**)&stf, g_stf);
    cudaGetSymbolAddress((void**)&spf, g_spf);
    cudaGetSymbolAddress((void**)&uf,  g_uf);

    f16 *tdh, *tdl, *zh, *zl, *sph, *spl, *sth, *stl, *rsh, *rsl, *xh, *xl;
    cudaGetSymbolAddress((void**)&tdh, g_tdh); cudaGetSymbolAddress((void**)&tdl, g_tdl);
    cudaGetSymbolAddress((void**)&zh,  g_zh);  cudaGetSymbolAddress((void**)&zl,  g_zl);
    cudaGetSymbolAddress((void**)&sph, g_sph); cudaGetSymbolAddress((void**)&spl, g_spl);
    cudaGetSymbolAddress((void**)&sth, g_sth); cudaGetSymbolAddress((void**)&stl, g_stl);
    cudaGetSymbolAddress((void**)&rsh, g_rsh); cudaGetSymbolAddress((void**)&rsl, g_rsl);
    cudaGetSymbolAddress((void**)&xh,  g_xh);  cudaGetSymbolAddress((void**)&xl,  g_xl);

    f16 *W12h, *W3h, *Wbh, *Woh, *Wzh;
    cudaGetSymbolAddress((void**)&W12h, g_W12h);
    cudaGetSymbolAddress((void**)&W3h,  g_W3h);
    cudaGetSymbolAddress((void**)&Wbh,  g_Wbh);
    cudaGetSymbolAddress((void**)&Woh,  g_Woh);
    cudaGetSymbolAddress((void**)&Wzh,  g_Wzh);

    cudaFuncSetAttribute(tgemm<EPI_LIN>,   cudaFuncAttributeMaxDynamicSharedMemorySize, SMEM_T);
    cudaFuncSetAttribute(tgemm<EPI_BELTA>, cudaFuncAttributeMaxDynamicSharedMemorySize, SMEM_T);
    cudaFuncSetAttribute(tgemm<EPI_SIGUR>, cudaFuncAttributeMaxDynamicSharedMemorySize, SMEM_T);
    cudaFuncSetAttribute(tgemm<EPI_NEW>,   cudaFuncAttributeMaxDynamicSharedMemorySize, SMEM_T);

    // ---- per-launch prep (deterministic for graph replay) ----
    zero_kernel<<<(B_DIM * H_DIM + 1023) / 1024, 1024>>>(stf, B_DIM * H_DIM);
    {
        int n4 = (B_DIM * LDO) / 4;
        asplit<<<(n4 + 255) / 256, 256>>>(td, n4, tdh, tdl);
        n4 = (B_DIM * ZDIM) / 4;
        asplit<<<(n4 + 255) / 256, 256>>>(z, n4, zh, zl);
    }
    dim3 tb(32, 8);
    whalf<<<dim3(H_DIM / 32, CAT / 32),    tb>>>(W1,      CAT,    H_DIM,  W12h);
    whalf<<<dim3(H_DIM / 32, CAT / 32),    tb>>>(W2,      CAT,    H_DIM,  W12h + (size_t)H_DIM * CAT);
    whalf<<<dim3(H_DIM / 32, CAT / 32),    tb>>>(W3,      CAT,    H_DIM,  W3h);
    whalf<<<dim3(H_DIM / 32, IN_DIM / 32), tb>>>(W_belta, IN_DIM, H_DIM,  Wbh);
    whalf<<<dim3(IN_DIM / 32, H_DIM / 32), tb>>>(W_out,   H_DIM,  IN_DIM, Woh);
    whalf<<<dim3(IN_DIM / 32, ZDIM / 32),  tb>>>(W_z,     ZDIM,   IN_DIM, Wzh);

    const dim3 blk(256);
    const dim3 gridH (H_DIM / 128,  B_DIM / 256);   // (8, 16)  = 128 CTAs
    const dim3 gridH2(N12 / 128,    B_DIM / 256);   // (16, 16) = 256 CTAs
    const dim3 gridI (IN_DIM / 128, B_DIM / 256);   // (4, 16)  = 64 CTAs

    // x0 = z @ W_z + b_z  -> x hi/lo only
    tgemm<EPI_LIN><<<gridI, blk, SMEM_T>>>(zh, zl, ZDIM, ZDIM, nullptr, nullptr, 0, 0,
                                           Wzh, b_z, nullptr, nullptr, nullptr,
                                           nullptr, 0, xh, xl, IN_DIM);

    for (int t = 0; t < SEQ_LEN; t++) {
        // spre = exp(-relu(td_t @ W_belta + b)) * state   (fp32 + hi/lo)
        tgemm<EPI_BELTA><<<gridH, blk, SMEM_T>>>(tdh + (size_t)t * IN_DIM,
                                                 tdl + (size_t)t * IN_DIM, LDO, IN_DIM,
                                                 nullptr, nullptr, 0, 0,
                                                 Wbh, b_belta, nullptr, stf, nullptr,
                                                 spf, H_DIM, sph, spl, H_DIM);
        // fused: u = sig([spre|x]W1+b1) -> uf ;  rs = sig([spre|x]W2+b2)*spre -> hi/lo
        tgemm<EPI_SIGUR><<<gridH2, blk, SMEM_T>>>(sph, spl, H_DIM, H_DIM,
                                                  xh, xl, IN_DIM, IN_DIM,
                                                  W12h, b1, b2, spf, nullptr,
                                                  uf, H_DIM, rsh, rsl, H_DIM);
        // state = (1-u)*spre + u*tanh([rs|x] @ W3 + b3)   (fp32 + hi/lo)
        tgemm<EPI_NEW><<<gridH, blk, SMEM_T>>>(rsh, rsl, H_DIM, H_DIM,
                                               xh, xl, IN_DIM, IN_DIM,
                                               W3h, b3, nullptr, uf, spf,
                                               stf, H_DIM, sth, stl, H_DIM);
        // out_t = state @ W_out + b_out  (fp32 strided into d_out + x hi/lo feedback)
        tgemm<EPI_LIN><<<gridI, blk, SMEM_T>>>(sth, stl, H_DIM, H_DIM,
                                               nullptr, nullptr, 0, 0,
                                               Woh, b_out, nullptr, nullptr, nullptr,
                                               out + (size_t)t * IN_DIM, LDO,
                                               xh, xl, IN_DIM);
    }
}

// round 9
// speedup vs baseline: 1.3305x; 1.3305x over previous
#include <cuda_runtime.h>
#include <cuda_fp16.h>
#include <math.h>
#include <stdint.h>

#define B_DIM   4096
#define ZDIM    128
#define IN_DIM  512
#define H_DIM   1024
#define SEQ_LEN 12
#define CAT     (IN_DIM + H_DIM)
#define LDO     (SEQ_LEN * IN_DIM)
#define N12     (2 * H_DIM)
#define LBEL    (SEQ_LEN * H_DIM)

typedef __half  f16;
typedef __half2 f162;

// ---------------- scratch (__device__ globals; no allocs allowed) -----------
__device__ float g_bel[B_DIM * SEQ_LEN * H_DIM];   // 201 MB: belta, all steps
__device__ float g_spf[B_DIM * H_DIM];
__device__ float g_uf [B_DIM * H_DIM];

__device__ f16 g_tdh[B_DIM * LDO],    g_tdl[B_DIM * LDO];
__device__ f16 g_zh [B_DIM * ZDIM],   g_zl [B_DIM * ZDIM];
__device__ f16 g_sph[B_DIM * H_DIM],  g_spl[B_DIM * H_DIM];
__device__ f16 g_sth[B_DIM * H_DIM],  g_stl[B_DIM * H_DIM];
__device__ f16 g_rsh[B_DIM * H_DIM],  g_rsl[B_DIM * H_DIM];
__device__ f16 g_xh [B_DIM * IN_DIM], g_xl [B_DIM * IN_DIM];

// weights transposed to [N][K] fp16 (hi only — 2-term scheme)
__device__ f16 g_W12h[N12 * CAT];          // W1 rows then W2 rows
__device__ f16 g_W3h [H_DIM * CAT];
__device__ f16 g_Wbh [H_DIM * IN_DIM];
__device__ f16 g_Woh [IN_DIM * H_DIM];
__device__ f16 g_Wzh [IN_DIM * ZDIM];

enum { EPI_LIN = 0, EPI_BELTAPRE = 1, EPI_SIGUR = 2, EPI_NEW = 3 };

// ---------------- prep kernels ---------------------------------------------
__global__ void zero_kernel(float* __restrict__ p, int n) {
    int i = blockIdx.x * blockDim.x + threadIdx.x;
    if (i < n) p[i] = 0.0f;
}

__global__ void asplit(const float* __restrict__ X, int n4,
                       f16* __restrict__ H, f16* __restrict__ L) {
    int i = blockIdx.x * blockDim.x + threadIdx.x;
    if (i >= n4) return;
    float4 v = ((const float4*)X)[i];
    f16 h0 = __float2half_rn(v.x), h1 = __float2half_rn(v.y);
    f16 h2 = __float2half_rn(v.z), h3 = __float2half_rn(v.w);
    f162 H0; H0.x = h0; H0.y = h1;
    f162 H1; H1.x = h2; H1.y = h3;
    f162 L0, L1;
    L0.x = __float2half_rn(v.x - __half2float(h0));
    L0.y = __float2half_rn(v.y - __half2float(h1));
    L1.x = __float2half_rn(v.z - __half2float(h2));
    L1.y = __float2half_rn(v.w - __half2float(h3));
    ((f162*)H)[2 * i] = H0; ((f162*)H)[2 * i + 1] = H1;
    ((f162*)L)[2 * i] = L0; ((f162*)L)[2 * i + 1] = L1;
}

__global__ void whalf(const float* __restrict__ W, int K, int N,
                      f16* __restrict__ Th) {
    __shared__ float t[32][33];
    const int n0 = blockIdx.x * 32, k0 = blockIdx.y * 32;
    const int tx = threadIdx.x, ty = threadIdx.y;   // (32, 8)
#pragma unroll
    for (int j = 0; j < 32; j += 8)
        t[ty + j][tx] = W[(size_t)(k0 + ty + j) * N + (n0 + tx)];
    __syncthreads();
#pragma unroll
    for (int j = 0; j < 32; j += 8)
        Th[(size_t)(n0 + ty + j) * K + (k0 + tx)] = __float2half_rn(t[tx][ty + j]);
}

// ---------------- PTX primitives --------------------------------------------
__device__ __forceinline__ uint32_t smem_u32(const void* p) {
    uint32_t a;
    asm("{ .reg .u64 t; cvta.to.shared.u64 t, %1; cvt.u32.u64 %0, t; }" : "=r"(a) : "l"(p));
    return a;
}

#define CP16(dst, src) \
    asm volatile("cp.async.ca.shared.global [%0], [%1], 16;" :: "r"(dst), "l"(src) : "memory")
#define CPCOMMIT() asm volatile("cp.async.commit_group;" ::: "memory")
#define CPWAIT1()  asm volatile("cp.async.wait_group 1;"  ::: "memory")

#define LDSM4(r, a) \
    asm volatile("ldmatrix.sync.aligned.m8n8.x4.shared.b16 {%0,%1,%2,%3}, [%4];" \
        : "=r"((r)[0]), "=r"((r)[1]), "=r"((r)[2]), "=r"((r)[3]) : "r"(a))

#define MMA(c, a, b0, b1) \
    asm volatile("mma.sync.aligned.m16n8k16.row.col.f32.f16.f16.f32 " \
        "{%0,%1,%2,%3}, {%4,%5,%6,%7}, {%8,%9}, {%0,%1,%2,%3};" \
        : "+f"((c)[0]), "+f"((c)[1]), "+f"((c)[2]), "+f"((c)[3]) \
        : "r"((a)[0]), "r"((a)[1]), "r"((a)[2]), "r"((a)[3]), "r"(b0), "r"(b1))

// ---------------- HMMA GEMM with fused epilogue -----------------------------
// CTA tile 128x128, 8 warps = 4(M) x 2(N), warp tile 32x64, occ 2 (R7 core).
#define KC      32
#define AROW80  80
#define TILE_B  (128 * AROW80)           // 10240 B
#define STAGE   (3 * TILE_B)             // Ahi, Alo, Bhi
#define NSTG    3
#define SMEM_T  (NSTG * STAGE)           // 92160 B

template <int EPI>
__global__ __launch_bounds__(256, 2)
void tgemm(const f16* __restrict__ Ah1, const f16* __restrict__ Al1, int lda1, int K1,
           const f16* __restrict__ Ah2, const f16* __restrict__ Al2, int lda2, int K2,
           const f16* __restrict__ Bh,
           const float* __restrict__ bias, const float* __restrict__ bias2,
           const float* __restrict__ ex1, const float* __restrict__ ex2,
           const float* __restrict__ exB,        // NEW: belta[t+1] base (or null)
           float* __restrict__ Cf, int ldcf,
           f16* __restrict__ Ch, f16* __restrict__ Cl, int ldch,
           float* __restrict__ C2f,              // NEW: spre fp32
           f16* __restrict__ C2h, f16* __restrict__ C2l)
{
    extern __shared__ __align__(128) char smem[];
    const uint32_t sb = smem_u32(smem);
    const int tid = threadIdx.x;
    const int bm = blockIdx.y * 128, bn = blockIdx.x * 128;
    const int Ktot = K1 + K2;
    const int KT = Ktot / KC;

    const int cr = tid >> 1;
    const int cs = (tid & 1) * 2;

    auto issue = [&](int c, int s) {
        const int ks = c * KC;
        const f16 *ah, *al;
        if (ks < K1) {
            ah = Ah1 + (size_t)(bm + cr) * lda1 + ks;
            al = Al1 + (size_t)(bm + cr) * lda1 + ks;
        } else {
            ah = Ah2 + (size_t)(bm + cr) * lda2 + (ks - K1);
            al = Al2 + (size_t)(bm + cr) * lda2 + (ks - K1);
        }
        const f16* bh = Bh + (size_t)(bn + cr) * Ktot + ks;
        const uint32_t base = sb + (uint32_t)s * STAGE + (uint32_t)cr * AROW80;
#pragma unroll
        for (int g = 0; g < 2; g++) {
            const int seg = cs + g;
            const uint32_t off = (uint32_t)seg * 16u;
            CP16(base + 0 * TILE_B + off, ah + seg * 8);
            CP16(base + 1 * TILE_B + off, al + seg * 8);
            CP16(base + 2 * TILE_B + off, bh + seg * 8);
        }
    };

    const int warp = tid >> 5, lane = tid & 31;
    const int wm = (warp & 3) * 32;
    const int wn = (warp >> 2) * 64;
    const int lr = lane & 7;
    const uint32_t aBase = (uint32_t)(wm + lr + ((lane >> 3) & 1) * 8) * AROW80
                         + (uint32_t)(((lane >> 4) & 1) * 8) * 2;
    const uint32_t bBase = (uint32_t)(wn + lr + ((lane >> 4) & 1) * 8) * AROW80
                         + (uint32_t)(((lane >> 3) & 1) * 8) * 2;

    float acc[2][8][4];
#pragma unroll
    for (int mi = 0; mi < 2; mi++)
#pragma unroll
        for (int j = 0; j < 8; j++)
#pragma unroll
            for (int q = 0; q < 4; q++) acc[mi][j][q] = 0.0f;

    issue(0, 0); CPCOMMIT();
    issue(1, 1); CPCOMMIT();

    for (int c = 0; c < KT; c++) {
        CPWAIT1();
        __syncthreads();
        if (c + 2 < KT) issue(c + 2, (c + 2) % NSTG);
        CPCOMMIT();
        const uint32_t st = sb + (uint32_t)(c % NSTG) * STAGE;
#pragma unroll
        for (int k2 = 0; k2 < 2; k2++) {
            uint32_t ah[2][4], al[2][4];
#pragma unroll
            for (int mi = 0; mi < 2; mi++) {
                const uint32_t ao = st + aBase + (uint32_t)mi * (16 * AROW80)
                                  + (uint32_t)k2 * 32;
                LDSM4(ah[mi], ao);
                LDSM4(al[mi], ao + TILE_B);
            }
#pragma unroll
            for (int jj = 0; jj < 4; jj++) {
                uint32_t b4[4];
                const uint32_t bo = st + 2 * TILE_B + bBase
                                  + (uint32_t)jj * (16 * AROW80) + (uint32_t)k2 * 32;
                LDSM4(b4, bo);
                MMA(acc[0][2 * jj],     ah[0], b4[0], b4[1]);
                MMA(acc[1][2 * jj],     ah[1], b4[0], b4[1]);
                MMA(acc[0][2 * jj],     al[0], b4[0], b4[1]);
                MMA(acc[1][2 * jj],     al[1], b4[0], b4[1]);
                MMA(acc[0][2 * jj + 1], ah[0], b4[2], b4[3]);
                MMA(acc[1][2 * jj + 1], ah[1], b4[2], b4[3]);
                MMA(acc[0][2 * jj + 1], al[0], b4[2], b4[3]);
                MMA(acc[1][2 * jj + 1], al[1], b4[2], b4[3]);
            }
        }
    }

    // --- epilogue ---
    const int r0 = bm + wm + (lane >> 2);
    const int c0 = bn + wn + 2 * (lane & 3);

    auto split2 = [&](f16* Hp, f16* Lp, size_t off, float v0, float v1) {
        f16 h0 = __float2half_rn(v0), h1 = __float2half_rn(v1);
        f162 hh; hh.x = h0; hh.y = h1;
        f162 ll;
        ll.x = __float2half_rn(v0 - __half2float(h0));
        ll.y = __float2half_rn(v1 - __half2float(h1));
        *(f162*)(Hp + off) = hh;
        *(f162*)(Lp + off) = ll;
    };

    auto dopair = [&](int row, int col, float v0, float v1) {
        if (EPI == EPI_SIGUR) {
            if (col < H_DIM) {
                float2 bs = *(const float2*)(bias + col);
                v0 = 1.0f / (1.0f + __expf(-(v0 + bs.x)));
                v1 = 1.0f / (1.0f + __expf(-(v1 + bs.y)));
                *(float2*)(Cf + (size_t)row * ldcf + col) = make_float2(v0, v1);
            } else {
                const int cc = col - H_DIM;
                float2 bs = *(const float2*)(bias2 + cc);
                float2 e  = *(const float2*)(ex1 + (size_t)row * H_DIM + cc);
                v0 = e.x / (1.0f + __expf(-(v0 + bs.x)));
                v1 = e.y / (1.0f + __expf(-(v1 + bs.y)));
                split2(Ch, Cl, (size_t)row * ldch + cc, v0, v1);
            }
            return;
        }
        float2 bs = *(const float2*)(bias + col);
        v0 += bs.x; v1 += bs.y;
        if (EPI == EPI_BELTAPRE) {
            v0 = __expf(-fmaxf(v0, 0.0f));
            v1 = __expf(-fmaxf(v1, 0.0f));
            *(float2*)(Cf + (size_t)row * ldcf + col) = make_float2(v0, v1);
            return;
        }
        if (EPI == EPI_NEW) {
            float2 eu = *(const float2*)(ex1 + (size_t)row * H_DIM + col);
            float2 es = *(const float2*)(ex2 + (size_t)row * H_DIM + col);
            float s0 = (1.0f - eu.x) * es.x + eu.x * tanhf(v0);
            float s1 = (1.0f - eu.y) * es.y + eu.y * tanhf(v1);
            split2(Ch, Cl, (size_t)row * ldch + col, s0, s1);
            if (exB) {
                float2 bl2 = *(const float2*)(exB + (size_t)row * LBEL + col);
                float sp0 = bl2.x * s0, sp1 = bl2.y * s1;
                *(float2*)(C2f + (size_t)row * H_DIM + col) = make_float2(sp0, sp1);
                split2(C2h, C2l, (size_t)row * H_DIM + col, sp0, sp1);
            }
            return;
        }
        // EPI_LIN
        if (Cf) *(float2*)(Cf + (size_t)row * ldcf + col) = make_float2(v0, v1);
        if (Ch) split2(Ch, Cl, (size_t)row * ldch + col, v0, v1);
    };

#pragma unroll
    for (int mi = 0; mi < 2; mi++)
#pragma unroll
        for (int j = 0; j < 8; j++) {
            const int row = r0 + mi * 16;
            const int col = c0 + j * 8;
            dopair(row,     col, acc[mi][j][0], acc[mi][j][1]);
            dopair(row + 8, col, acc[mi][j][2], acc[mi][j][3]);
        }
}

// ---------------- host -------------------------------------------------------
extern "C" void kernel_launch(void* const* d_in, const int* in_sizes, int n_in,
                              void* d_out, int out_size)
{
    const float* z       = (const float*)d_in[0];
    const float* td      = (const float*)d_in[1];
    const float* W_belta = (const float*)d_in[2];
    const float* b_belta = (const float*)d_in[3];
    const float* W_z     = (const float*)d_in[4];
    const float* b_z     = (const float*)d_in[5];
    const float* W1      = (const float*)d_in[6];
    const float* b1      = (const float*)d_in[7];
    const float* W2      = (const float*)d_in[8];
    const float* b2      = (const float*)d_in[9];
    const float* W3      = (const float*)d_in[10];
    const float* b3      = (const float*)d_in[11];
    const float* W_out   = (const float*)d_in[12];
    const float* b_out   = (const float*)d_in[13];
    float* out = (float*)d_out;

    float *bel, *spf, *uf;
    cudaGetSymbolAddress((void**)&bel, g_bel);
    cudaGetSymbolAddress((void**)&spf, g_spf);
    cudaGetSymbolAddress((void**)&uf,  g_uf);

    f16 *tdh, *tdl, *zh, *zl, *sph, *spl, *sth, *stl, *rsh, *rsl, *xh, *xl;
    cudaGetSymbolAddress((void**)&tdh, g_tdh); cudaGetSymbolAddress((void**)&tdl, g_tdl);
    cudaGetSymbolAddress((void**)&zh,  g_zh);  cudaGetSymbolAddress((void**)&zl,  g_zl);
    cudaGetSymbolAddress((void**)&sph, g_sph); cudaGetSymbolAddress((void**)&spl, g_spl);
    cudaGetSymbolAddress((void**)&sth, g_sth); cudaGetSymbolAddress((void**)&stl, g_stl);
    cudaGetSymbolAddress((void**)&rsh, g_rsh); cudaGetSymbolAddress((void**)&rsl, g_rsl);
    cudaGetSymbolAddress((void**)&xh,  g_xh);  cudaGetSymbolAddress((void**)&xl,  g_xl);

    f16 *W12h, *W3h, *Wbh, *Woh, *Wzh;
    cudaGetSymbolAddress((void**)&W12h, g_W12h);
    cudaGetSymbolAddress((void**)&W3h,  g_W3h);
    cudaGetSymbolAddress((void**)&Wbh,  g_Wbh);
    cudaGetSymbolAddress((void**)&Woh,  g_Woh);
    cudaGetSymbolAddress((void**)&Wzh,  g_Wzh);

    cudaFuncSetAttribute(tgemm<EPI_LIN>,      cudaFuncAttributeMaxDynamicSharedMemorySize, SMEM_T);
    cudaFuncSetAttribute(tgemm<EPI_BELTAPRE>, cudaFuncAttributeMaxDynamicSharedMemorySize, SMEM_T);
    cudaFuncSetAttribute(tgemm<EPI_SIGUR>,    cudaFuncAttributeMaxDynamicSharedMemorySize, SMEM_T);
    cudaFuncSetAttribute(tgemm<EPI_NEW>,      cudaFuncAttributeMaxDynamicSharedMemorySize, SMEM_T);

    // ---- per-launch prep (deterministic for graph replay) ----
    // spre_0 = belta_0 * 0 = 0  ->  zero spf/sph/spl
    zero_kernel<<<(B_DIM * H_DIM + 1023) / 1024, 1024>>>(spf, B_DIM * H_DIM);
    zero_kernel<<<(B_DIM * H_DIM / 2 + 1023) / 1024, 1024>>>((float*)sph, B_DIM * H_DIM / 2);
    zero_kernel<<<(B_DIM * H_DIM / 2 + 1023) / 1024, 1024>>>((float*)spl, B_DIM * H_DIM / 2);
    {
        int n4 = (B_DIM * LDO) / 4;
        asplit<<<(n4 + 255) / 256, 256>>>(td, n4, tdh, tdl);
        n4 = (B_DIM * ZDIM) / 4;
        asplit<<<(n4 + 255) / 256, 256>>>(z, n4, zh, zl);
    }
    dim3 tb(32, 8);
    whalf<<<dim3(H_DIM / 32, CAT / 32),    tb>>>(W1,      CAT,    H_DIM,  W12h);
    whalf<<<dim3(H_DIM / 32, CAT / 32),    tb>>>(W2,      CAT,    H_DIM,  W12h + (size_t)H_DIM * CAT);
    whalf<<<dim3(H_DIM / 32, CAT / 32),    tb>>>(W3,      CAT,    H_DIM,  W3h);
    whalf<<<dim3(H_DIM / 32, IN_DIM / 32), tb>>>(W_belta, IN_DIM, H_DIM,  Wbh);
    whalf<<<dim3(IN_DIM / 32, H_DIM / 32), tb>>>(W_out,   H_DIM,  IN_DIM, Woh);
    whalf<<<dim3(IN_DIM / 32, ZDIM / 32),  tb>>>(W_z,     ZDIM,   IN_DIM, Wzh);

    const dim3 blk(256);
    const dim3 gridB (H_DIM / 128,  (B_DIM * SEQ_LEN) / 128);  // (8, 384) big belta
    const dim3 gridH (H_DIM / 128,  B_DIM / 128);              // (8, 32)
    const dim3 gridH2(N12 / 128,    B_DIM / 128);              // (16, 32)
    const dim3 gridI (IN_DIM / 128, B_DIM / 128);              // (4, 32)

    // bel = exp(-relu(td @ W_belta + b))  for ALL steps at once
    // td viewed as (B*S, IN_DIM) contiguous; bel as (B*S, H_DIM)
    tgemm<EPI_BELTAPRE><<<gridB, blk, SMEM_T>>>(tdh, tdl, IN_DIM, IN_DIM,
                                                nullptr, nullptr, 0, 0,
                                                Wbh, b_belta, nullptr,
                                                nullptr, nullptr, nullptr,
                                                bel, H_DIM, nullptr, nullptr, 0,
                                                nullptr, nullptr, nullptr);

    // x0 = z @ W_z + b_z  -> x hi/lo only
    tgemm<EPI_LIN><<<gridI, blk, SMEM_T>>>(zh, zl, ZDIM, ZDIM, nullptr, nullptr, 0, 0,
                                           Wzh, b_z, nullptr, nullptr, nullptr, nullptr,
                                           nullptr, 0, xh, xl, IN_DIM,
                                           nullptr, nullptr, nullptr);

    for (int t = 0; t < SEQ_LEN; t++) {
        // fused: u = sig([spre|x]W1+b1) -> uf ;  rs = sig([spre|x]W2+b2)*spre
        tgemm<EPI_SIGUR><<<gridH2, blk, SMEM_T>>>(sph, spl, H_DIM, H_DIM,
                                                  xh, xl, IN_DIM, IN_DIM,
                                                  W12h, b1, b2, spf, nullptr, nullptr,
                                                  uf, H_DIM, rsh, rsl, H_DIM,
                                                  nullptr, nullptr, nullptr);
        // state = (1-u)*spre + u*tanh([rs|x]W3+b3); also spre' = belta[t+1]*state
        const float* belN = (t + 1 < SEQ_LEN) ? bel + (size_t)(t + 1) * H_DIM : nullptr;
        tgemm<EPI_NEW><<<gridH, blk, SMEM_T>>>(rsh, rsl, H_DIM, H_DIM,
                                               xh, xl, IN_DIM, IN_DIM,
                                               W3h, b3, nullptr, uf, spf, belN,
                                               nullptr, 0, sth, stl, H_DIM,
                                               spf, sph, spl);
        // out_t = state @ W_out + b_out  (fp32 strided into d_out + x hi/lo feedback)
        tgemm<EPI_LIN><<<gridI, blk, SMEM_T>>>(sth, stl, H_DIM, H_DIM,
                                               nullptr, nullptr, 0, 0,
                                               Woh, b_out, nullptr, nullptr, nullptr, nullptr,
                                               out + (size_t)t * IN_DIM, LDO,
                                               xh, xl, IN_DIM,
                                               nullptr, nullptr, nullptr);
    }
}